// round 2
// baseline (speedup 1.0000x reference)
#include <cuda_runtime.h>
#include <cuda_bf16.h>
#include <math.h>

// ---------------- problem constants ----------------
#define BB     32
#define CC     128
#define HH     64
#define WW_    64
#define WS     8
#define SHIFT  4
#define HEADS  4
#define DH     32          // CC/HEADS
#define HID    512         // 4*CC
#define METAH  256
#define TOK    64          // WS*WS
#define NW     64          // (H/WS)*(W/WS)
#define BW     2048        // BB*NW
#define BTOK   131072      // BW*TOK  ( = BB*HH*WW_ )
#define HW     4096        // HH*WW_

// ---------------- scratch (device globals; no cudaMalloc allowed) ----------------
// Buffer lifetime plan (aliasing to keep footprint modest):
//   g_xin  : x transposed [B,HW,C]          — live until merge_ln1
//   g_buf0 : xw tokens, then attn out       — xw dead after QKV gemm, reused for att
//   g_qkv  : qkv [BTOK,384], then ffn1 uses first BTOK*512?? (384<512, cannot alias) -> separate
//   g_ffn1 : [BTOK,512]
//   g_om   : proj out, later ffn2 out, later final pre-transpose (sequenced reuse is safe:
//            om dead after merge_ln1; ffn2 written by gemm_ffn2, read by ln2_res -> then tmp
//            must be a different buffer than ffn2's source? ln2_res reads g_om(ffn2) and
//            writes g_tmp; keep tmp separate to avoid RW hazard within one kernel row —
//            actually each row reads then writes same row only, but keep separate for safety.
static __device__ __align__(16) float g_xin [BTOK * CC];      // 64 MB
static __device__ __align__(16) float g_buf0[BTOK * CC];      // 64 MB  (xw / att)
static __device__ __align__(16) float g_qkv [BTOK * 3 * CC];  // 192 MB
static __device__ __align__(16) float g_ffn1[BTOK * HID];     // 256 MB
static __device__ __align__(16) float g_om  [BTOK * CC];      // 64 MB  (proj out / ffn2 out)
static __device__ __align__(16) float g_skip[BTOK * CC];      // 64 MB
static __device__ __align__(16) float g_tmp [BTOK * CC];      // 64 MB
static __device__ __align__(16) float g_bias[HEADS * TOK * TOK];

// ---------------- helpers ----------------
__device__ __forceinline__ float warp_sum(float v) {
    #pragma unroll
    for (int o = 16; o > 0; o >>= 1) v += __shfl_xor_sync(0xffffffffu, v, o);
    return v;
}

__device__ __forceinline__ float gelu_exact(float x) {
    return 0.5f * x * (1.0f + erff(x * 0.70710678118654752440f));
}

// ---------------- transpose [B,C,HW] -> [B,HW,C] ----------------
__global__ __launch_bounds__(256) void transpose_in_kernel(const float* __restrict__ x) {
    __shared__ float sm[32][33];
    int b   = blockIdx.z;
    int hw0 = blockIdx.x * 32;
    int c0  = blockIdx.y * 32;
    int tx  = threadIdx.x, ty = threadIdx.y;
    #pragma unroll
    for (int i = ty; i < 32; i += 8)
        sm[i][tx] = x[(size_t)b * CC * HW + (size_t)(c0 + i) * HW + hw0 + tx];
    __syncthreads();
    #pragma unroll
    for (int i = ty; i < 32; i += 8)
        g_xin[(size_t)(b * HW + hw0 + i) * CC + c0 + tx] = sm[tx][i];
}

// ---------------- transpose [B,HW,C] -> [B,C,HW] ----------------
__global__ __launch_bounds__(256) void transpose_out_kernel(float* __restrict__ out) {
    __shared__ float sm[32][33];
    int b   = blockIdx.z;
    int hw0 = blockIdx.x * 32;
    int c0  = blockIdx.y * 32;
    int tx  = threadIdx.x, ty = threadIdx.y;
    #pragma unroll
    for (int i = ty; i < 32; i += 8)
        sm[i][tx] = g_tmp[(size_t)(b * HW + hw0 + i) * CC + c0 + tx];
    __syncthreads();
    #pragma unroll
    for (int i = ty; i < 32; i += 8)
        out[(size_t)b * CC * HW + (size_t)(c0 + i) * HW + hw0 + tx] = sm[tx][i];
}

// ---------------- shifted window gather: g_xin -> g_buf0 ----------------
// xw[bw, t, c] = xin[b, (wh*8+th+4)&63, (ww*8+tw+4)&63, c]
__global__ __launch_bounds__(256) void gather_kernel() {
    int r = blockIdx.x * 8 + threadIdx.y;   // token row 0..131071
    int bw = r >> 6, t = r & 63;
    int b = bw >> 6, widx = bw & 63;
    int wh = widx >> 3, ww = widx & 7;
    int th = t >> 3, tw = t & 7;
    int h = (wh * 8 + th + SHIFT) & 63;
    int w = (ww * 8 + tw + SHIFT) & 63;
    const float4* src = (const float4*)(g_xin + (size_t)(b * HW + h * 64 + w) * CC);
    float4* dst = (float4*)(g_buf0 + (size_t)r * CC);
    dst[threadIdx.x] = src[threadIdx.x];    // 32 threads x float4 = 128 floats
}

// ---------------- meta MLP relative-position bias table ----------------
__global__ void meta_kernel(const float* __restrict__ w1, const float* __restrict__ b1,
                            const float* __restrict__ w2, const float* __restrict__ b2) {
    int pq = blockIdx.x * 256 + threadIdx.x;      // 0..4095
    int p = pq >> 6, q = pq & 63;
    float d0 = (float)((p >> 3) - (q >> 3));
    float d1 = (float)((p & 7) - (q & 7));
    float r0 = (d0 > 0.f ? 1.f : (d0 < 0.f ? -1.f : 0.f)) * log1pf(fabsf(d0));
    float r1 = (d1 > 0.f ? 1.f : (d1 < 0.f ? -1.f : 0.f)) * log1pf(fabsf(d1));
    float acc0 = 0.f, acc1 = 0.f, acc2 = 0.f, acc3 = 0.f;
    for (int j = 0; j < METAH; j++) {
        float hv = fmaxf(r0 * w1[j] + r1 * w1[METAH + j] + b1[j], 0.f);
        acc0 += hv * w2[j * 4 + 0];
        acc1 += hv * w2[j * 4 + 1];
        acc2 += hv * w2[j * 4 + 2];
        acc3 += hv * w2[j * 4 + 3];
    }
    g_bias[0 * 4096 + pq] = acc0 + b2[0];
    g_bias[1 * 4096 + pq] = acc1 + b2[1];
    g_bias[2 * 4096 + pq] = acc2 + b2[2];
    g_bias[3 * 4096 + pq] = acc3 + b2[3];
}

// ---------------- generic fp32 GEMM body: C = act(A[M,128*?] @ B[K,N] + bias) ----------------
// BM=BN=128, BK=16, 256 threads, 8x8 per thread. N,K compile-time.
template <int ACT, int N, int K>
__device__ __forceinline__ void gemm_body(const float* __restrict__ A,
                                          const float* __restrict__ B,
                                          const float* __restrict__ bias,
                                          float* __restrict__ C) {
    __shared__ float As[16][132];
    __shared__ float Bs[16][132];
    const int tid = threadIdx.x;
    const int tx = tid & 15, ty = tid >> 4;
    const int m0 = blockIdx.y * 128, n0 = blockIdx.x * 128;

    float acc[8][8];
    #pragma unroll
    for (int i = 0; i < 8; i++)
        #pragma unroll
        for (int j = 0; j < 8; j++) acc[i][j] = 0.f;

    #pragma unroll 1
    for (int k0 = 0; k0 < K; k0 += 16) {
        #pragma unroll
        for (int it = 0; it < 2; it++) {
            int id = tid + it * 256;
            int m = id >> 2, kq = (id & 3) << 2;
            float4 v = *(const float4*)(A + (size_t)(m0 + m) * K + k0 + kq);
            As[kq + 0][m] = v.x; As[kq + 1][m] = v.y;
            As[kq + 2][m] = v.z; As[kq + 3][m] = v.w;
        }
        #pragma unroll
        for (int it = 0; it < 2; it++) {
            int id = tid + it * 256;
            int kk = id >> 5, nq = (id & 31) << 2;
            float4 v = *(const float4*)(B + (size_t)(k0 + kk) * N + n0 + nq);
            *(float4*)&Bs[kk][nq] = v;
        }
        __syncthreads();
        #pragma unroll
        for (int k = 0; k < 16; k++) {
            float af[8], bf[8];
            *(float4*)(af)     = *(const float4*)&As[k][ty * 8];
            *(float4*)(af + 4) = *(const float4*)&As[k][ty * 8 + 4];
            *(float4*)(bf)     = *(const float4*)&Bs[k][tx * 8];
            *(float4*)(bf + 4) = *(const float4*)&Bs[k][tx * 8 + 4];
            #pragma unroll
            for (int i = 0; i < 8; i++)
                #pragma unroll
                for (int j = 0; j < 8; j++) acc[i][j] += af[i] * bf[j];
        }
        __syncthreads();
    }

    #pragma unroll
    for (int i = 0; i < 8; i++) {
        int row = m0 + ty * 8 + i;
        #pragma unroll
        for (int j = 0; j < 8; j += 4) {
            int col = n0 + tx * 8 + j;
            float4 r;
            r.x = acc[i][j + 0] + bias[col + 0];
            r.y = acc[i][j + 1] + bias[col + 1];
            r.z = acc[i][j + 2] + bias[col + 2];
            r.w = acc[i][j + 3] + bias[col + 3];
            if (ACT == 1) {
                r.x = gelu_exact(r.x); r.y = gelu_exact(r.y);
                r.z = gelu_exact(r.z); r.w = gelu_exact(r.w);
            }
            *(float4*)(C + (size_t)row * N + col) = r;
        }
    }
}

// GEMM wrappers — fixed buffers, weights as params
__global__ __launch_bounds__(256) void gemm_qkv_kernel(const float* __restrict__ w,
                                                       const float* __restrict__ b) {
    gemm_body<0, 384, 128>(g_buf0, w, b, g_qkv);
}
__global__ __launch_bounds__(256) void gemm_proj_kernel(const float* __restrict__ w,
                                                        const float* __restrict__ b) {
    gemm_body<0, 128, 128>(g_buf0, w, b, g_om);
}
__global__ __launch_bounds__(256) void gemm_ffn1_kernel(const float* __restrict__ w,
                                                        const float* __restrict__ b) {
    gemm_body<1, 512, 128>(g_skip, w, b, g_ffn1);
}
__global__ __launch_bounds__(256) void gemm_ffn2_kernel(const float* __restrict__ w,
                                                        const float* __restrict__ b) {
    gemm_body<0, 128, 512>(g_ffn1, w, b, g_om);
}

// ---------------- per-(window,head) attention ----------------
// reads g_qkv + g_bias, writes g_buf0 (xw is dead by now)
__global__ __launch_bounds__(256) void attn_kernel(const float* __restrict__ tau) {
    const int bw = blockIdx.x;
    const int head = blockIdx.y;
    __shared__ float qs[64][33];
    __shared__ float ks[64][33];
    __shared__ float vs[64][33];
    __shared__ float S[64][65];
    __shared__ float qn[64], kn[64];
    __shared__ int cnt[64];
    const int tid = threadIdx.x;

    // load q,k,v tiles (each thread: 8 contiguous d of one row)
    {
        int i = tid >> 2;
        int ds = (tid & 3) << 3;
        const float* rp = g_qkv + (size_t)(bw * 64 + i) * 384 + head * 32 + ds;
        float4 a = *(const float4*)(rp);
        float4 b = *(const float4*)(rp + 4);
        qs[i][ds+0]=a.x; qs[i][ds+1]=a.y; qs[i][ds+2]=a.z; qs[i][ds+3]=a.w;
        qs[i][ds+4]=b.x; qs[i][ds+5]=b.y; qs[i][ds+6]=b.z; qs[i][ds+7]=b.w;
        a = *(const float4*)(rp + 128);
        b = *(const float4*)(rp + 132);
        ks[i][ds+0]=a.x; ks[i][ds+1]=a.y; ks[i][ds+2]=a.z; ks[i][ds+3]=a.w;
        ks[i][ds+4]=b.x; ks[i][ds+5]=b.y; ks[i][ds+6]=b.z; ks[i][ds+7]=b.w;
        a = *(const float4*)(rp + 256);
        b = *(const float4*)(rp + 260);
        vs[i][ds+0]=a.x; vs[i][ds+1]=a.y; vs[i][ds+2]=a.z; vs[i][ds+3]=a.w;
        vs[i][ds+4]=b.x; vs[i][ds+5]=b.y; vs[i][ds+6]=b.z; vs[i][ds+7]=b.w;
    }
    __syncthreads();

    if (tid < 64) {
        float s = 0.f;
        #pragma unroll
        for (int d = 0; d < 32; d++) { float v = qs[tid][d]; s += v * v; }
        qn[tid] = sqrtf(s);
        s = 0.f;
        #pragma unroll
        for (int d = 0; d < 32; d++) { float v = ks[tid][d]; s += v * v; }
        kn[tid] = sqrtf(s);
        int widx = bw & 63;
        int gh = (widx >> 3) * 8 + (tid >> 3);
        int gw = (widx & 7) * 8 + (tid & 7);
        int rh = gh < 56 ? 0 : (gh < 60 ? 1 : 2);
        int rw = gw < 56 ? 0 : (gw < 60 ? 1 : 2);
        cnt[tid] = rh * 3 + rw;
    }
    __syncthreads();

    const float inv_tau = 1.0f / fmaxf(tau[head], 0.01f);

    // S = (q k^T) / max(|q||k|,1e-6) / tau + bias + mask   (4x4 per thread)
    {
        int ib = (tid >> 4) << 2;
        int jb = (tid & 15) << 2;
        float acc[4][4];
        #pragma unroll
        for (int u = 0; u < 4; u++)
            #pragma unroll
            for (int v = 0; v < 4; v++) acc[u][v] = 0.f;
        #pragma unroll
        for (int d = 0; d < 32; d++) {
            float qa[4], ka[4];
            #pragma unroll
            for (int u = 0; u < 4; u++) { qa[u] = qs[ib + u][d]; ka[u] = ks[jb + u][d]; }
            #pragma unroll
            for (int u = 0; u < 4; u++)
                #pragma unroll
                for (int v = 0; v < 4; v++) acc[u][v] += qa[u] * ka[v];
        }
        const float* bp = g_bias + (head << 12);
        #pragma unroll
        for (int u = 0; u < 4; u++)
            #pragma unroll
            for (int v = 0; v < 4; v++) {
                int i = ib + u, j = jb + v;
                float den = fmaxf(qn[i] * kn[j], 1e-6f);
                float sc = acc[u][v] / den * inv_tau + bp[i * 64 + j];
                if (cnt[i] != cnt[j]) sc -= 100.0f;
                S[i][j] = sc;
            }
    }
    __syncthreads();

    // softmax per row
    if (tid < 64) {
        float m = -1e30f;
        #pragma unroll
        for (int j = 0; j < 64; j++) m = fmaxf(m, S[tid][j]);
        float s = 0.f;
        #pragma unroll
        for (int j = 0; j < 64; j++) { float e = expf(S[tid][j] - m); S[tid][j] = e; s += e; }
        float inv = 1.0f / s;
        #pragma unroll
        for (int j = 0; j < 64; j++) S[tid][j] *= inv;
    }
    __syncthreads();

    // O = S @ V  (8 d-columns per thread)
    {
        int i = tid >> 2;
        int db = (tid & 3) << 3;
        float acc[8];
        #pragma unroll
        for (int dd = 0; dd < 8; dd++) acc[dd] = 0.f;
        #pragma unroll
        for (int j = 0; j < 64; j++) {
            float p = S[i][j];
            #pragma unroll
            for (int dd = 0; dd < 8; dd++) acc[dd] += p * vs[j][db + dd];
        }
        float* op = g_buf0 + (size_t)(bw * 64 + i) * 128 + head * 32 + db;
        #pragma unroll
        for (int dd = 0; dd < 8; dd++) op[dd] = acc[dd];
    }
}

// ---------------- fold + roll-back + LN1 + residual ----------------
// reads g_om (proj out, window token order) + g_xin, writes g_skip
__global__ __launch_bounds__(256) void merge_ln1_kernel(const float* __restrict__ g,
                                                        const float* __restrict__ b) {
    int warp = threadIdx.x >> 5, lane = threadIdx.x & 31;
    int r = blockIdx.x * 8 + warp;                 // b*4096 + h*64 + w
    int bb = r >> 12;
    int hw = r & 4095;
    int h = hw >> 6, w = hw & 63;
    int hs = (h - SHIFT) & 63, ws = (w - SHIFT) & 63;
    int omrow = (bb * 64 + (hs >> 3) * 8 + (ws >> 3)) * 64 + (hs & 7) * 8 + (ws & 7);
    float4 v = ((const float4*)g_om)[(size_t)omrow * 32 + lane];
    float s = v.x + v.y + v.z + v.w;
    s = warp_sum(s);
    float mu = s * (1.0f / 128.0f);
    float dx = v.x - mu, dy = v.y - mu, dz = v.z - mu, dw = v.w - mu;
    float s2 = dx * dx + dy * dy + dz * dz + dw * dw;
    s2 = warp_sum(s2);
    float rstd = rsqrtf(s2 * (1.0f / 128.0f) + 1e-5f);
    float4 gg = ((const float4*)g)[lane];
    float4 bv = ((const float4*)b)[lane];
    float4 xi = ((const float4*)g_xin)[(size_t)r * 32 + lane];
    float4 o;
    o.x = xi.x + dx * rstd * gg.x + bv.x;
    o.y = xi.y + dy * rstd * gg.y + bv.y;
    o.z = xi.z + dz * rstd * gg.z + bv.z;
    o.w = xi.w + dw * rstd * gg.w + bv.w;
    ((float4*)g_skip)[(size_t)r * 32 + lane] = o;
}

// ---------------- LN2 + residual ----------------
// reads g_om (ffn2 out) + g_skip, writes g_tmp
__global__ __launch_bounds__(256) void ln2_res_kernel(const float* __restrict__ g,
                                                      const float* __restrict__ b) {
    int warp = threadIdx.x >> 5, lane = threadIdx.x & 31;
    int r = blockIdx.x * 8 + warp;
    float4 v = ((const float4*)g_om)[(size_t)r * 32 + lane];
    float s = v.x + v.y + v.z + v.w;
    s = warp_sum(s);
    float mu = s * (1.0f / 128.0f);
    float dx = v.x - mu, dy = v.y - mu, dz = v.z - mu, dw = v.w - mu;
    float s2 = dx * dx + dy * dy + dz * dz + dw * dw;
    s2 = warp_sum(s2);
    float rstd = rsqrtf(s2 * (1.0f / 128.0f) + 1e-5f);
    float4 gg = ((const float4*)g)[lane];
    float4 bv = ((const float4*)b)[lane];
    float4 rr = ((const float4*)g_skip)[(size_t)r * 32 + lane];
    float4 o;
    o.x = rr.x + dx * rstd * gg.x + bv.x;
    o.y = rr.y + dy * rstd * gg.y + bv.y;
    o.z = rr.z + dz * rstd * gg.z + bv.z;
    o.w = rr.w + dw * rstd * gg.w + bv.w;
    ((float4*)g_tmp)[(size_t)r * 32 + lane] = o;
}

// ---------------- launch: kernel launches ONLY ----------------
extern "C" void kernel_launch(void* const* d_in, const int* in_sizes, int n_in,
                              void* d_out, int out_size) {
    const float* x      = (const float*)d_in[0];
    const float* qkv_w  = (const float*)d_in[1];
    const float* qkv_b  = (const float*)d_in[2];
    const float* proj_w = (const float*)d_in[3];
    const float* proj_b = (const float*)d_in[4];
    const float* mw1    = (const float*)d_in[5];
    const float* mb1    = (const float*)d_in[6];
    const float* mw2    = (const float*)d_in[7];
    const float* mb2    = (const float*)d_in[8];
    const float* tau    = (const float*)d_in[9];
    const float* ln1g   = (const float*)d_in[10];
    const float* ln1b   = (const float*)d_in[11];
    const float* ln2g   = (const float*)d_in[12];
    const float* ln2b   = (const float*)d_in[13];
    const float* fw1    = (const float*)d_in[14];
    const float* fb1    = (const float*)d_in[15];
    const float* fw2    = (const float*)d_in[16];
    const float* fb2    = (const float*)d_in[17];
    float* out = (float*)d_out;

    dim3 tb(32, 8);
    dim3 tg(HW / 32, CC / 32, BB);

    transpose_in_kernel<<<tg, tb>>>(x);
    gather_kernel<<<BTOK / 8, tb>>>();
    meta_kernel<<<16, 256>>>(mw1, mb1, mw2, mb2);

    gemm_qkv_kernel<<<dim3(3, BTOK / 128), 256>>>(qkv_w, qkv_b);

    attn_kernel<<<dim3(BW, HEADS), 256>>>(tau);

    gemm_proj_kernel<<<dim3(1, BTOK / 128), 256>>>(proj_w, proj_b);

    merge_ln1_kernel<<<BTOK / 8, 256>>>(ln1g, ln1b);

    gemm_ffn1_kernel<<<dim3(4, BTOK / 128), 256>>>(fw1, fb1);
    gemm_ffn2_kernel<<<dim3(1, BTOK / 128), 256>>>(fw2, fb2);

    ln2_res_kernel<<<BTOK / 8, 256>>>(ln2g, ln2b);

    transpose_out_kernel<<<tg, tb>>>(out);
}

// round 3
// speedup vs baseline: 1.5760x; 1.5760x over previous
#include <cuda_runtime.h>
#include <cuda_bf16.h>
#include <math.h>

// ---------------- problem constants ----------------
#define BB     32
#define CC     128
#define HH     64
#define WW_    64
#define WS     8
#define SHIFT  4
#define HEADS  4
#define DH     32          // CC/HEADS
#define HID    512         // 4*CC
#define METAH  256
#define TOK    64          // WS*WS
#define NW     64          // (H/WS)*(W/WS)
#define BW     2048        // BB*NW
#define BTOK   131072      // BW*TOK  ( = BB*HH*WW_ )
#define HW     4096        // HH*WW_

// ---------------- scratch (device globals; no cudaMalloc allowed) ----------------
static __device__ __align__(16) float g_xin [BTOK * CC];      // 64 MB
static __device__ __align__(16) float g_buf0[BTOK * CC];      // 64 MB  (xw / att)
static __device__ __align__(16) float g_qkv [BTOK * 3 * CC];  // 192 MB
static __device__ __align__(16) float g_ffn1[BTOK * HID];     // 256 MB
static __device__ __align__(16) float g_om  [BTOK * CC];      // 64 MB  (proj out / ffn2 out)
static __device__ __align__(16) float g_skip[BTOK * CC];      // 64 MB
static __device__ __align__(16) float g_tmp [BTOK * CC];      // 64 MB
static __device__ __align__(16) float g_bias[HEADS * TOK * TOK];

// ---------------- helpers ----------------
__device__ __forceinline__ float warp_sum(float v) {
    #pragma unroll
    for (int o = 16; o > 0; o >>= 1) v += __shfl_xor_sync(0xffffffffu, v, o);
    return v;
}

__device__ __forceinline__ float gelu_exact(float x) {
    return 0.5f * x * (1.0f + erff(x * 0.70710678118654752440f));
}

__device__ __forceinline__ unsigned f2tf32(float f) {
    unsigned r;
    asm("cvt.rna.tf32.f32 %0, %1;" : "=r"(r) : "f"(f));
    return r;
}

__device__ __forceinline__ void mma_tf32(float& c0, float& c1, float& c2, float& c3,
                                         unsigned a0, unsigned a1, unsigned a2, unsigned a3,
                                         unsigned b0, unsigned b1) {
    asm volatile(
        "mma.sync.aligned.m16n8k8.row.col.f32.tf32.tf32.f32 "
        "{%0,%1,%2,%3}, {%4,%5,%6,%7}, {%8,%9}, {%0,%1,%2,%3};\n"
        : "+f"(c0), "+f"(c1), "+f"(c2), "+f"(c3)
        : "r"(a0), "r"(a1), "r"(a2), "r"(a3), "r"(b0), "r"(b1));
}

// ---------------- transpose [B,C,HW] -> [B,HW,C] ----------------
__global__ __launch_bounds__(256) void transpose_in_kernel(const float* __restrict__ x) {
    __shared__ float sm[32][33];
    int b   = blockIdx.z;
    int hw0 = blockIdx.x * 32;
    int c0  = blockIdx.y * 32;
    int tx  = threadIdx.x, ty = threadIdx.y;
    #pragma unroll
    for (int i = ty; i < 32; i += 8)
        sm[i][tx] = x[(size_t)b * CC * HW + (size_t)(c0 + i) * HW + hw0 + tx];
    __syncthreads();
    #pragma unroll
    for (int i = ty; i < 32; i += 8)
        g_xin[(size_t)(b * HW + hw0 + i) * CC + c0 + tx] = sm[tx][i];
}

// ---------------- transpose [B,HW,C] -> [B,C,HW] ----------------
__global__ __launch_bounds__(256) void transpose_out_kernel(float* __restrict__ out) {
    __shared__ float sm[32][33];
    int b   = blockIdx.z;
    int hw0 = blockIdx.x * 32;
    int c0  = blockIdx.y * 32;
    int tx  = threadIdx.x, ty = threadIdx.y;
    #pragma unroll
    for (int i = ty; i < 32; i += 8)
        sm[i][tx] = g_tmp[(size_t)(b * HW + hw0 + i) * CC + c0 + tx];
    __syncthreads();
    #pragma unroll
    for (int i = ty; i < 32; i += 8)
        out[(size_t)b * CC * HW + (size_t)(c0 + i) * HW + hw0 + tx] = sm[tx][i];
}

// ---------------- shifted window gather: g_xin -> g_buf0 ----------------
__global__ __launch_bounds__(256) void gather_kernel() {
    int r = blockIdx.x * 8 + threadIdx.y;   // token row 0..131071
    int bw = r >> 6, t = r & 63;
    int b = bw >> 6, widx = bw & 63;
    int wh = widx >> 3, ww = widx & 7;
    int th = t >> 3, tw = t & 7;
    int h = (wh * 8 + th + SHIFT) & 63;
    int w = (ww * 8 + tw + SHIFT) & 63;
    const float4* src = (const float4*)(g_xin + (size_t)(b * HW + h * 64 + w) * CC);
    float4* dst = (float4*)(g_buf0 + (size_t)r * CC);
    dst[threadIdx.x] = src[threadIdx.x];    // 32 threads x float4 = 128 floats
}

// ---------------- meta MLP relative-position bias table ----------------
__global__ void meta_kernel(const float* __restrict__ w1, const float* __restrict__ b1,
                            const float* __restrict__ w2, const float* __restrict__ b2) {
    int pq = blockIdx.x * 256 + threadIdx.x;      // 0..4095
    int p = pq >> 6, q = pq & 63;
    float d0 = (float)((p >> 3) - (q >> 3));
    float d1 = (float)((p & 7) - (q & 7));
    float r0 = (d0 > 0.f ? 1.f : (d0 < 0.f ? -1.f : 0.f)) * log1pf(fabsf(d0));
    float r1 = (d1 > 0.f ? 1.f : (d1 < 0.f ? -1.f : 0.f)) * log1pf(fabsf(d1));
    float acc0 = 0.f, acc1 = 0.f, acc2 = 0.f, acc3 = 0.f;
    for (int j = 0; j < METAH; j++) {
        float hv = fmaxf(r0 * w1[j] + r1 * w1[METAH + j] + b1[j], 0.f);
        acc0 += hv * w2[j * 4 + 0];
        acc1 += hv * w2[j * 4 + 1];
        acc2 += hv * w2[j * 4 + 2];
        acc3 += hv * w2[j * 4 + 3];
    }
    g_bias[0 * 4096 + pq] = acc0 + b2[0];
    g_bias[1 * 4096 + pq] = acc1 + b2[1];
    g_bias[2 * 4096 + pq] = acc2 + b2[2];
    g_bias[3 * 4096 + pq] = acc3 + b2[3];
}

// ---------------- tf32 tensor-core GEMM: C = act(A[M,K] @ B[K,N] + bias) ----------------
// BM=BN=128, BK=32, 256 threads (8 warps: 4 along M x 2 along N, warp tile 32x64).
// mma.sync.m16n8k8 tf32, fp32 accumulate. Inputs rounded to tf32 (cvt.rna) on LDG->STS.
template <int ACT, int N, int K>
__device__ __forceinline__ void gemm_tc_body(const float* __restrict__ A,
                                             const float* __restrict__ B,
                                             const float* __restrict__ bias,
                                             float* __restrict__ C) {
    __shared__ unsigned As[32][132];   // [k][m]
    __shared__ unsigned Bs[32][132];   // [k][n]
    const int tid  = threadIdx.x;
    const int warp = tid >> 5, lane = tid & 31;
    const int gid  = lane >> 2, tig = lane & 3;
    const int wm   = (warp & 3) * 32;   // warp m-offset
    const int wn   = (warp >> 2) * 64;  // warp n-offset
    const int m0   = blockIdx.y * 128, n0 = blockIdx.x * 128;

    float c[2][8][4];
    #pragma unroll
    for (int mt = 0; mt < 2; mt++)
        #pragma unroll
        for (int nt = 0; nt < 8; nt++)
            #pragma unroll
            for (int r = 0; r < 4; r++) c[mt][nt][r] = 0.f;

    #pragma unroll 1
    for (int k0 = 0; k0 < K; k0 += 32) {
        // A tile 128x32: 1024 float4 loads; store transposed [k][m] with tf32 rounding
        #pragma unroll
        for (int it = 0; it < 4; it++) {
            int id = tid + it * 256;
            int m = id >> 3, kq = (id & 7) << 2;
            float4 v = *(const float4*)(A + (size_t)(m0 + m) * K + k0 + kq);
            As[kq + 0][m] = f2tf32(v.x);
            As[kq + 1][m] = f2tf32(v.y);
            As[kq + 2][m] = f2tf32(v.z);
            As[kq + 3][m] = f2tf32(v.w);
        }
        // B tile 32x128: [k][n], row-contiguous
        #pragma unroll
        for (int it = 0; it < 4; it++) {
            int id = tid + it * 256;
            int kk = id >> 5, nq = (id & 31) << 2;
            float4 v = *(const float4*)(B + (size_t)(k0 + kk) * N + n0 + nq);
            uint4 u;
            u.x = f2tf32(v.x); u.y = f2tf32(v.y);
            u.z = f2tf32(v.z); u.w = f2tf32(v.w);
            *(uint4*)&Bs[kk][nq] = u;
        }
        __syncthreads();

        #pragma unroll
        for (int ks = 0; ks < 32; ks += 8) {
            unsigned a[2][4], b[8][2];
            #pragma unroll
            for (int mt = 0; mt < 2; mt++) {
                int mr = wm + mt * 16 + gid;
                a[mt][0] = As[ks + tig][mr];
                a[mt][1] = As[ks + tig][mr + 8];
                a[mt][2] = As[ks + tig + 4][mr];
                a[mt][3] = As[ks + tig + 4][mr + 8];
            }
            #pragma unroll
            for (int nt = 0; nt < 8; nt++) {
                int nc = wn + nt * 8 + gid;
                b[nt][0] = Bs[ks + tig][nc];
                b[nt][1] = Bs[ks + tig + 4][nc];
            }
            #pragma unroll
            for (int mt = 0; mt < 2; mt++)
                #pragma unroll
                for (int nt = 0; nt < 8; nt++)
                    mma_tf32(c[mt][nt][0], c[mt][nt][1], c[mt][nt][2], c[mt][nt][3],
                             a[mt][0], a[mt][1], a[mt][2], a[mt][3],
                             b[nt][0], b[nt][1]);
        }
        __syncthreads();
    }

    // epilogue: bias (+ optional GELU), float2 stores
    #pragma unroll
    for (int mt = 0; mt < 2; mt++) {
        int row0 = m0 + wm + mt * 16 + gid;
        #pragma unroll
        for (int nt = 0; nt < 8; nt++) {
            int col = n0 + wn + nt * 8 + tig * 2;
            float b0 = bias[col], b1 = bias[col + 1];
            float v0 = c[mt][nt][0] + b0;
            float v1 = c[mt][nt][1] + b1;
            float v2 = c[mt][nt][2] + b0;
            float v3 = c[mt][nt][3] + b1;
            if (ACT == 1) {
                v0 = gelu_exact(v0); v1 = gelu_exact(v1);
                v2 = gelu_exact(v2); v3 = gelu_exact(v3);
            }
            float2 p0; p0.x = v0; p0.y = v1;
            float2 p1; p1.x = v2; p1.y = v3;
            *(float2*)(C + (size_t)row0 * N + col) = p0;
            *(float2*)(C + (size_t)(row0 + 8) * N + col) = p1;
        }
    }
}

// GEMM wrappers — fixed buffers, weights as params
__global__ __launch_bounds__(256, 2) void gemm_qkv_kernel(const float* __restrict__ w,
                                                          const float* __restrict__ b) {
    gemm_tc_body<0, 384, 128>(g_buf0, w, b, g_qkv);
}
__global__ __launch_bounds__(256, 2) void gemm_proj_kernel(const float* __restrict__ w,
                                                           const float* __restrict__ b) {
    gemm_tc_body<0, 128, 128>(g_buf0, w, b, g_om);
}
__global__ __launch_bounds__(256, 2) void gemm_ffn1_kernel(const float* __restrict__ w,
                                                           const float* __restrict__ b) {
    gemm_tc_body<1, 512, 128>(g_skip, w, b, g_ffn1);
}
__global__ __launch_bounds__(256, 2) void gemm_ffn2_kernel(const float* __restrict__ w,
                                                           const float* __restrict__ b) {
    gemm_tc_body<0, 128, 512>(g_ffn1, w, b, g_om);
}

// ---------------- per-(window,head) attention ----------------
// reads g_qkv + g_bias, writes g_buf0 (xw is dead by now)
__global__ __launch_bounds__(256) void attn_kernel(const float* __restrict__ tau) {
    const int bw = blockIdx.x;
    const int head = blockIdx.y;
    __shared__ float qs[64][33];
    __shared__ float ks[64][33];
    __shared__ float vs[64][33];
    __shared__ float S[64][65];
    __shared__ float qn[64], kn[64];
    __shared__ int cnt[64];
    const int tid = threadIdx.x;

    {
        int i = tid >> 2;
        int ds = (tid & 3) << 3;
        const float* rp = g_qkv + (size_t)(bw * 64 + i) * 384 + head * 32 + ds;
        float4 a = *(const float4*)(rp);
        float4 b = *(const float4*)(rp + 4);
        qs[i][ds+0]=a.x; qs[i][ds+1]=a.y; qs[i][ds+2]=a.z; qs[i][ds+3]=a.w;
        qs[i][ds+4]=b.x; qs[i][ds+5]=b.y; qs[i][ds+6]=b.z; qs[i][ds+7]=b.w;
        a = *(const float4*)(rp + 128);
        b = *(const float4*)(rp + 132);
        ks[i][ds+0]=a.x; ks[i][ds+1]=a.y; ks[i][ds+2]=a.z; ks[i][ds+3]=a.w;
        ks[i][ds+4]=b.x; ks[i][ds+5]=b.y; ks[i][ds+6]=b.z; ks[i][ds+7]=b.w;
        a = *(const float4*)(rp + 256);
        b = *(const float4*)(rp + 260);
        vs[i][ds+0]=a.x; vs[i][ds+1]=a.y; vs[i][ds+2]=a.z; vs[i][ds+3]=a.w;
        vs[i][ds+4]=b.x; vs[i][ds+5]=b.y; vs[i][ds+6]=b.z; vs[i][ds+7]=b.w;
    }
    __syncthreads();

    if (tid < 64) {
        float s = 0.f;
        #pragma unroll
        for (int d = 0; d < 32; d++) { float v = qs[tid][d]; s += v * v; }
        qn[tid] = sqrtf(s);
        s = 0.f;
        #pragma unroll
        for (int d = 0; d < 32; d++) { float v = ks[tid][d]; s += v * v; }
        kn[tid] = sqrtf(s);
        int widx = bw & 63;
        int gh = (widx >> 3) * 8 + (tid >> 3);
        int gw = (widx & 7) * 8 + (tid & 7);
        int rh = gh < 56 ? 0 : (gh < 60 ? 1 : 2);
        int rw = gw < 56 ? 0 : (gw < 60 ? 1 : 2);
        cnt[tid] = rh * 3 + rw;
    }
    __syncthreads();

    const float inv_tau = 1.0f / fmaxf(tau[head], 0.01f);

    {
        int ib = (tid >> 4) << 2;
        int jb = (tid & 15) << 2;
        float acc[4][4];
        #pragma unroll
        for (int u = 0; u < 4; u++)
            #pragma unroll
            for (int v = 0; v < 4; v++) acc[u][v] = 0.f;
        #pragma unroll
        for (int d = 0; d < 32; d++) {
            float qa[4], ka[4];
            #pragma unroll
            for (int u = 0; u < 4; u++) { qa[u] = qs[ib + u][d]; ka[u] = ks[jb + u][d]; }
            #pragma unroll
            for (int u = 0; u < 4; u++)
                #pragma unroll
                for (int v = 0; v < 4; v++) acc[u][v] += qa[u] * ka[v];
        }
        const float* bp = g_bias + (head << 12);
        #pragma unroll
        for (int u = 0; u < 4; u++)
            #pragma unroll
            for (int v = 0; v < 4; v++) {
                int i = ib + u, j = jb + v;
                float den = fmaxf(qn[i] * kn[j], 1e-6f);
                float sc = acc[u][v] / den * inv_tau + bp[i * 64 + j];
                if (cnt[i] != cnt[j]) sc -= 100.0f;
                S[i][j] = sc;
            }
    }
    __syncthreads();

    if (tid < 64) {
        float m = -1e30f;
        #pragma unroll
        for (int j = 0; j < 64; j++) m = fmaxf(m, S[tid][j]);
        float s = 0.f;
        #pragma unroll
        for (int j = 0; j < 64; j++) { float e = expf(S[tid][j] - m); S[tid][j] = e; s += e; }
        float inv = 1.0f / s;
        #pragma unroll
        for (int j = 0; j < 64; j++) S[tid][j] *= inv;
    }
    __syncthreads();

    {
        int i = tid >> 2;
        int db = (tid & 3) << 3;
        float acc[8];
        #pragma unroll
        for (int dd = 0; dd < 8; dd++) acc[dd] = 0.f;
        #pragma unroll
        for (int j = 0; j < 64; j++) {
            float p = S[i][j];
            #pragma unroll
            for (int dd = 0; dd < 8; dd++) acc[dd] += p * vs[j][db + dd];
        }
        float* op = g_buf0 + (size_t)(bw * 64 + i) * 128 + head * 32 + db;
        #pragma unroll
        for (int dd = 0; dd < 8; dd++) op[dd] = acc[dd];
    }
}

// ---------------- fold + roll-back + LN1 + residual ----------------
__global__ __launch_bounds__(256) void merge_ln1_kernel(const float* __restrict__ g,
                                                        const float* __restrict__ b) {
    int warp = threadIdx.x >> 5, lane = threadIdx.x & 31;
    int r = blockIdx.x * 8 + warp;                 // b*4096 + h*64 + w
    int bb = r >> 12;
    int hw = r & 4095;
    int h = hw >> 6, w = hw & 63;
    int hs = (h - SHIFT) & 63, ws = (w - SHIFT) & 63;
    int omrow = (bb * 64 + (hs >> 3) * 8 + (ws >> 3)) * 64 + (hs & 7) * 8 + (ws & 7);
    float4 v = ((const float4*)g_om)[(size_t)omrow * 32 + lane];
    float s = v.x + v.y + v.z + v.w;
    s = warp_sum(s);
    float mu = s * (1.0f / 128.0f);
    float dx = v.x - mu, dy = v.y - mu, dz = v.z - mu, dw = v.w - mu;
    float s2 = dx * dx + dy * dy + dz * dz + dw * dw;
    s2 = warp_sum(s2);
    float rstd = rsqrtf(s2 * (1.0f / 128.0f) + 1e-5f);
    float4 gg = ((const float4*)g)[lane];
    float4 bv = ((const float4*)b)[lane];
    float4 xi = ((const float4*)g_xin)[(size_t)r * 32 + lane];
    float4 o;
    o.x = xi.x + dx * rstd * gg.x + bv.x;
    o.y = xi.y + dy * rstd * gg.y + bv.y;
    o.z = xi.z + dz * rstd * gg.z + bv.z;
    o.w = xi.w + dw * rstd * gg.w + bv.w;
    ((float4*)g_skip)[(size_t)r * 32 + lane] = o;
}

// ---------------- LN2 + residual ----------------
__global__ __launch_bounds__(256) void ln2_res_kernel(const float* __restrict__ g,
                                                      const float* __restrict__ b) {
    int warp = threadIdx.x >> 5, lane = threadIdx.x & 31;
    int r = blockIdx.x * 8 + warp;
    float4 v = ((const float4*)g_om)[(size_t)r * 32 + lane];
    float s = v.x + v.y + v.z + v.w;
    s = warp_sum(s);
    float mu = s * (1.0f / 128.0f);
    float dx = v.x - mu, dy = v.y - mu, dz = v.z - mu, dw = v.w - mu;
    float s2 = dx * dx + dy * dy + dz * dz + dw * dw;
    s2 = warp_sum(s2);
    float rstd = rsqrtf(s2 * (1.0f / 128.0f) + 1e-5f);
    float4 gg = ((const float4*)g)[lane];
    float4 bv = ((const float4*)b)[lane];
    float4 rr = ((const float4*)g_skip)[(size_t)r * 32 + lane];
    float4 o;
    o.x = rr.x + dx * rstd * gg.x + bv.x;
    o.y = rr.y + dy * rstd * gg.y + bv.y;
    o.z = rr.z + dz * rstd * gg.z + bv.z;
    o.w = rr.w + dw * rstd * gg.w + bv.w;
    ((float4*)g_tmp)[(size_t)r * 32 + lane] = o;
}

// ---------------- launch: kernel launches ONLY ----------------
extern "C" void kernel_launch(void* const* d_in, const int* in_sizes, int n_in,
                              void* d_out, int out_size) {
    const float* x      = (const float*)d_in[0];
    const float* qkv_w  = (const float*)d_in[1];
    const float* qkv_b  = (const float*)d_in[2];
    const float* proj_w = (const float*)d_in[3];
    const float* proj_b = (const float*)d_in[4];
    const float* mw1    = (const float*)d_in[5];
    const float* mb1    = (const float*)d_in[6];
    const float* mw2    = (const float*)d_in[7];
    const float* mb2    = (const float*)d_in[8];
    const float* tau    = (const float*)d_in[9];
    const float* ln1g   = (const float*)d_in[10];
    const float* ln1b   = (const float*)d_in[11];
    const float* ln2g   = (const float*)d_in[12];
    const float* ln2b   = (const float*)d_in[13];
    const float* fw1    = (const float*)d_in[14];
    const float* fb1    = (const float*)d_in[15];
    const float* fw2    = (const float*)d_in[16];
    const float* fb2    = (const float*)d_in[17];
    float* out = (float*)d_out;

    dim3 tb(32, 8);
    dim3 tg(HW / 32, CC / 32, BB);

    transpose_in_kernel<<<tg, tb>>>(x);
    gather_kernel<<<BTOK / 8, tb>>>();
    meta_kernel<<<16, 256>>>(mw1, mb1, mw2, mb2);

    gemm_qkv_kernel<<<dim3(3, BTOK / 128), 256>>>(qkv_w, qkv_b);

    attn_kernel<<<dim3(BW, HEADS), 256>>>(tau);

    gemm_proj_kernel<<<dim3(1, BTOK / 128), 256>>>(proj_w, proj_b);

    merge_ln1_kernel<<<BTOK / 8, 256>>>(ln1g, ln1b);

    gemm_ffn1_kernel<<<dim3(4, BTOK / 128), 256>>>(fw1, fb1);
    gemm_ffn2_kernel<<<dim3(1, BTOK / 128), 256>>>(fw2, fb2);

    ln2_res_kernel<<<BTOK / 8, 256>>>(ln2g, ln2b);

    transpose_out_kernel<<<tg, tb>>>(out);
}